// round 3
// baseline (speedup 1.0000x reference)
#include <cuda_runtime.h>
#include <math.h>

#define NIMG 48            // B*C = 16*3
#define NBATCH 16
#define N 1024
#define OUT_HW 224
// antialiased triangle kernel: support radius = inv_scale = 1024/224
#define KRAD (1024.0f/224.0f)
#define KSCL (224.0f/1024.0f)

// scratch (static device arrays; no allocation allowed)
__device__ float2 g_A[(size_t)NIMG * N * N];        // row-FFT output [img][y][kx]
__device__ float2 g_B[(size_t)NIMG * N * N];        // transposed     [img][kx][y]
__device__ float  g_T[(size_t)NIMG * N * OUT_HW];   // ky-resized     [img][kxs][oy]
__device__ unsigned int g_mn[NBATCH];
__device__ unsigned int g_mx[NBATCH];

__device__ __forceinline__ float2 cmul(float2 a, float2 b) {
    return make_float2(a.x*b.x - a.y*b.y, a.x*b.y + a.y*b.x);
}
__device__ __forceinline__ float2 cadd(float2 a, float2 b){ return make_float2(a.x+b.x, a.y+b.y); }
__device__ __forceinline__ float2 csub(float2 a, float2 b){ return make_float2(a.x-b.x, a.y-b.y); }

// base-4 digit reversal of a 10-bit index (1024 = 4^5)
__device__ __forceinline__ int rev4_10(int i) {
    return ((i & 3) << 8) | ((i & 12) << 4) | (i & 48) | ((i >> 4) & 12) | ((i >> 8) & 3);
}

// twiddle table tw[j] = exp(-2*pi*i*j/1024), j in [0,768)
__device__ __forceinline__ void fill_tw(float2* tw, int tid) {
    for (int j = tid; j < 768; j += 256) {
        float s, c;
        sincosf(-6.283185307179586f * (float)j / 1024.0f, &s, &c);
        tw[j] = make_float2(c, s);
    }
}

// in-place radix-4 DIT FFT, 1024 points, input digit-reversed. 256 threads.
__device__ __forceinline__ void fft1024_r4(float2* s, const float2* tw, int tid) {
    #pragma unroll
    for (int st = 0; st < 5; ++st) {
        int quarter = 1 << (2*st);
        int pos  = tid & (quarter - 1);
        int base = ((tid - pos) << 2) + pos;
        int tstep = 256 >> (2*st);           // N/len
        float2 x0 = s[base];
        float2 x1 = s[base + quarter];
        float2 x2 = s[base + 2*quarter];
        float2 x3 = s[base + 3*quarter];
        if (st) {
            int ti = pos * tstep;
            x1 = cmul(tw[ti],     x1);
            x2 = cmul(tw[2*ti],   x2);
            x3 = cmul(tw[3*ti],   x3);
        }
        float2 u0 = cadd(x0, x2);
        float2 u1 = csub(x0, x2);
        float2 u2 = cadd(x1, x3);
        float2 u3 = csub(x1, x3);
        s[base]             = cadd(u0, u2);
        s[base + quarter]   = make_float2(u1.x + u3.y, u1.y - u3.x); // u1 - i*u3
        s[base + 2*quarter] = csub(u0, u2);
        s[base + 3*quarter] = make_float2(u1.x - u3.y, u1.y + u3.x); // u1 + i*u3
        __syncthreads();
    }
}

__global__ void k_init(void) {
    int t = threadIdx.x;
    if (t < NBATCH) { g_mn[t] = 0x7f800000u; g_mx[t] = 0u; }
}

__global__ void __launch_bounds__(256) k_rowfft(const float* __restrict__ in) {
    __shared__ float2 s[N];
    __shared__ float2 tw[768];
    int row = blockIdx.x;               // img*1024 + y
    int tid = threadIdx.x;
    fill_tw(tw, tid);
    const float* rp = in + (size_t)row * N;
    #pragma unroll
    for (int e = tid; e < N; e += 256)
        s[rev4_10(e)] = make_float2(rp[e], 0.0f);
    __syncthreads();
    fft1024_r4(s, tw, tid);
    float2* op = g_A + (size_t)row * N;
    #pragma unroll
    for (int e = tid; e < N; e += 256)
        op[e] = s[e];
}

__global__ void k_transpose(void) {
    __shared__ float2 tile[32][33];
    size_t imgoff = (size_t)blockIdx.z * N * N;
    int x0 = blockIdx.x * 32, y0 = blockIdx.y * 32;
    int tx = threadIdx.x, ty = threadIdx.y;
    #pragma unroll
    for (int dy = ty; dy < 32; dy += 8)
        tile[dy][tx] = g_A[imgoff + (size_t)(y0 + dy) * N + x0 + tx];
    __syncthreads();
    #pragma unroll
    for (int dy = ty; dy < 32; dy += 8)
        g_B[imgoff + (size_t)(x0 + dy) * N + y0 + tx] = tile[tx][dy];
}

__global__ void __launch_bounds__(256) k_colfft(void) {
    __shared__ float2 s[N];
    __shared__ float2 tw[768];
    __shared__ float  m[N];             // shifted log-magnitude over kys
    __shared__ float  rmn[8], rmx[8];
    int blk = blockIdx.x;               // img*1024 + kx
    int img = blk >> 10;
    int kx  = blk & (N - 1);
    int tid = threadIdx.x;
    fill_tw(tw, tid);
    const float2* cp = g_B + (size_t)blk * N;
    #pragma unroll
    for (int e = tid; e < N; e += 256)
        s[rev4_10(e)] = cp[e];
    __syncthreads();
    fft1024_r4(s, tw, tid);

    float mn = 3.4e38f, mx = 0.0f;
    #pragma unroll
    for (int e = tid; e < N; e += 256) {
        float2 v = s[e];
        float mag = log1pf(sqrtf(v.x*v.x + v.y*v.y));
        m[(e + 512) & (N - 1)] = mag;   // fftshift along ky
        mn = fminf(mn, mag); mx = fmaxf(mx, mag);
    }
    #pragma unroll
    for (int o = 16; o; o >>= 1) {
        mn = fminf(mn, __shfl_xor_sync(0xffffffffu, mn, o));
        mx = fmaxf(mx, __shfl_xor_sync(0xffffffffu, mx, o));
    }
    if ((tid & 31) == 0) { rmn[tid >> 5] = mn; rmx[tid >> 5] = mx; }
    __syncthreads();                    // also fences m[] for resize reads
    if (tid == 0) {
        float a = rmn[0], c = rmx[0];
        #pragma unroll
        for (int w = 1; w < 8; ++w) { a = fminf(a, rmn[w]); c = fmaxf(c, rmx[w]); }
        int b = img / 3;                // img = b*3 + channel
        atomicMin(&g_mn[b], __float_as_uint(a));
        atomicMax(&g_mx[b], __float_as_uint(c));
    }

    // antialiased triangle resize along kys (weights sum normalized, matches jax)
    if (tid < OUT_HW) {
        int kxs = (kx + 512) & (N - 1); // fftshift along kx
        float sf = ((float)tid + 0.5f) * (1024.0f/224.0f) - 0.5f;
        int i0 = max(0, (int)ceilf(sf - KRAD));
        int i1 = min(N - 1, (int)floorf(sf + KRAD));
        float acc = 0.0f, sw = 0.0f;
        for (int i = i0; i <= i1; ++i) {
            float w = fmaxf(0.0f, 1.0f - fabsf(sf - (float)i) * KSCL);
            acc += w * m[i]; sw += w;
        }
        g_T[((size_t)img * N + kxs) * OUT_HW + tid] = acc / sw;
    }
}

__global__ void __launch_bounds__(224) k_resize2(float* __restrict__ out) {
    int blk = blockIdx.x;               // img*224 + ox
    int img = blk / OUT_HW;
    int ox  = blk - img * OUT_HW;
    int oy  = threadIdx.x;
    float sf = ((float)ox + 0.5f) * (1024.0f/224.0f) - 0.5f;
    int i0 = max(0, (int)ceilf(sf - KRAD));
    int i1 = min(N - 1, (int)floorf(sf + KRAD));
    float acc = 0.0f, sw = 0.0f;
    const float* base = g_T + (size_t)img * N * OUT_HW + oy;
    for (int i = i0; i <= i1; ++i) {
        float w = fmaxf(0.0f, 1.0f - fabsf(sf - (float)i) * KSCL);
        acc += w * base[(size_t)i * OUT_HW]; sw += w;
    }
    int b = img / 3;
    float mn = __uint_as_float(g_mn[b]);
    float mx = __uint_as_float(g_mx[b]);
    float v = (acc / sw - mn) / (mx - mn + 1e-8f);
    out[((size_t)img * OUT_HW + oy) * OUT_HW + ox] = v;
}

extern "C" void kernel_launch(void* const* d_in, const int* in_sizes, int n_in,
                              void* d_out, int out_size) {
    (void)in_sizes; (void)n_in; (void)out_size;
    const float* in = (const float*)d_in[0];
    float* out = (float*)d_out;

    k_init<<<1, 32>>>();
    k_rowfft<<<NIMG * N, 256>>>(in);
    dim3 tg(N / 32, N / 32, NIMG), tb(32, 8);
    k_transpose<<<tg, tb>>>();
    k_colfft<<<NIMG * N, 256>>>();
    k_resize2<<<NIMG * OUT_HW, 224>>>(out);
}

// round 4
// speedup vs baseline: 1.9368x; 1.9368x over previous
#include <cuda_runtime.h>
#include <math.h>

#define NIMG 48            // B*C = 16*3
#define NBATCH 16
#define N 1024
#define OUT_HW 224
#define W 513              // kept kx columns (Hermitian half)
#define WP 520             // padded row stride for g_A (float2 units)
// antialiased triangle kernel: support radius = inv_scale = 1024/224
#define KRAD (1024.0f/224.0f)
#define KSCL (224.0f/1024.0f)

// scratch (static device arrays; no allocation allowed)
__device__ float2 g_A[(size_t)NIMG * N * WP];       // row-FFT output [img][y][kx 0..512]
__device__ float2 g_B[(size_t)NIMG * W * N];        // transposed     [img][kx][y]
__device__ float  g_T[(size_t)NIMG * N * OUT_HW];   // ky-resized     [img][kxs][oy]
__device__ float2 g_tw[768];
__device__ unsigned int g_mn[NBATCH];
__device__ unsigned int g_mx[NBATCH];

__device__ __forceinline__ float2 cmul(float2 a, float2 b) {
    return make_float2(a.x*b.x - a.y*b.y, a.x*b.y + a.y*b.x);
}
__device__ __forceinline__ float2 cadd(float2 a, float2 b){ return make_float2(a.x+b.x, a.y+b.y); }
__device__ __forceinline__ float2 csub(float2 a, float2 b){ return make_float2(a.x-b.x, a.y-b.y); }

// base-4 digit reversal of a 10-bit index (1024 = 4^5)
__device__ __forceinline__ int rev4_10(int i) {
    return ((i & 3) << 8) | ((i & 12) << 4) | (i & 48) | ((i >> 4) & 12) | ((i >> 8) & 3);
}

__device__ __forceinline__ void load_tw(float2* tw, int tid) {
    #pragma unroll
    for (int j = tid; j < 768; j += 256) tw[j] = g_tw[j];
}

// in-place radix-4 DIT FFT, 1024 points, input digit-reversed. 256 threads.
__device__ __forceinline__ void fft1024_r4(float2* s, const float2* tw, int tid) {
    #pragma unroll
    for (int st = 0; st < 5; ++st) {
        int quarter = 1 << (2*st);
        int pos  = tid & (quarter - 1);
        int base = ((tid - pos) << 2) + pos;
        int tstep = 256 >> (2*st);           // N/len
        float2 x0 = s[base];
        float2 x1 = s[base + quarter];
        float2 x2 = s[base + 2*quarter];
        float2 x3 = s[base + 3*quarter];
        if (st) {
            int ti = pos * tstep;
            x1 = cmul(tw[ti],     x1);
            x2 = cmul(tw[2*ti],   x2);
            x3 = cmul(tw[3*ti],   x3);
        }
        float2 u0 = cadd(x0, x2);
        float2 u1 = csub(x0, x2);
        float2 u2 = cadd(x1, x3);
        float2 u3 = csub(x1, x3);
        s[base]             = cadd(u0, u2);
        s[base + quarter]   = make_float2(u1.x + u3.y, u1.y - u3.x); // u1 - i*u3
        s[base + 2*quarter] = csub(u0, u2);
        s[base + 3*quarter] = make_float2(u1.x - u3.y, u1.y + u3.x); // u1 + i*u3
        __syncthreads();
    }
}

__global__ void k_init(void) {
    int t = threadIdx.x;
    if (t < NBATCH) { g_mn[t] = 0x7f800000u; g_mx[t] = 0u; }
    for (int j = t; j < 768; j += 256) {
        float s, c;
        sincosf(-6.283185307179586f * (float)j / 1024.0f, &s, &c);
        g_tw[j] = make_float2(c, s);
    }
}

// One block = two real rows (y, y+512) of one image, packed as one complex FFT.
__global__ void __launch_bounds__(256) k_rowfft(const float* __restrict__ in) {
    __shared__ float2 s[N];
    __shared__ float2 tw[768];
    int bx  = blockIdx.x;               // img*512 + ya
    int img = bx >> 9;
    int ya  = bx & 511;
    int yb  = ya + 512;
    int tid = threadIdx.x;
    load_tw(tw, tid);
    const float* ra = in + ((size_t)img * N + ya) * N;
    const float* rb = in + ((size_t)img * N + yb) * N;
    #pragma unroll
    for (int e = tid; e < N; e += 256)
        s[rev4_10(e)] = make_float2(ra[e], rb[e]);
    __syncthreads();
    fft1024_r4(s, tw, tid);
    // unpack the two real spectra; keep kx = 0..512 only (Hermitian half)
    float2* oa = g_A + ((size_t)img * N + ya) * WP;
    float2* ob = g_A + ((size_t)img * N + yb) * WP;
    for (int e = tid; e < W; e += 256) {
        float2 Z  = s[e];
        float2 Zm = s[(N - e) & (N - 1)];
        oa[e] = make_float2(0.5f * (Z.x + Zm.x), 0.5f * (Z.y - Zm.y));
        ob[e] = make_float2(0.5f * (Z.y + Zm.y), 0.5f * (Zm.x - Z.x));
    }
}

__global__ void k_transpose(void) {
    __shared__ float2 tile[32][33];
    int img = blockIdx.z;
    int x0 = blockIdx.x * 32, y0 = blockIdx.y * 32;
    int tx = threadIdx.x, ty = threadIdx.y;
    if (x0 + tx < W) {
        #pragma unroll
        for (int dy = ty; dy < 32; dy += 8)
            tile[dy][tx] = g_A[((size_t)img * N + (y0 + dy)) * WP + x0 + tx];
    }
    __syncthreads();
    #pragma unroll
    for (int dy = ty; dy < 32; dy += 8)
        if (x0 + dy < W)
            g_B[((size_t)img * W + (x0 + dy)) * N + y0 + tx] = tile[tx][dy];
}

// One block = one kept column kx (0..512). Emits TWO resized g_T rows:
// the column itself and its Hermitian mirror (index-flipped magnitudes).
__global__ void __launch_bounds__(256) k_colfft(void) {
    __shared__ float2 s[N];
    __shared__ float2 tw[768];
    __shared__ float  m[N];             // shifted log-magnitude over kys
    __shared__ float  rmn[8], rmx[8];
    int blk = blockIdx.x;               // img*513 + kx
    int img = blk / W;
    int kx  = blk - img * W;
    int tid = threadIdx.x;
    load_tw(tw, tid);
    const float2* cp = g_B + (size_t)blk * N;
    #pragma unroll
    for (int e = tid; e < N; e += 256)
        s[rev4_10(e)] = cp[e];
    __syncthreads();
    fft1024_r4(s, tw, tid);

    float mn = 3.4e38f, mx = 0.0f;
    #pragma unroll
    for (int e = tid; e < N; e += 256) {
        float2 v = s[e];
        float mag = log1pf(sqrtf(v.x*v.x + v.y*v.y));
        m[(e + 512) & (N - 1)] = mag;   // fftshift along ky
        mn = fminf(mn, mag); mx = fmaxf(mx, mag);
    }
    #pragma unroll
    for (int o = 16; o; o >>= 1) {
        mn = fminf(mn, __shfl_xor_sync(0xffffffffu, mn, o));
        mx = fmaxf(mx, __shfl_xor_sync(0xffffffffu, mx, o));
    }
    if ((tid & 31) == 0) { rmn[tid >> 5] = mn; rmx[tid >> 5] = mx; }
    __syncthreads();                    // also fences m[] for resize reads
    if (tid == 0) {
        float a = rmn[0], c = rmx[0];
        #pragma unroll
        for (int w = 1; w < 8; ++w) { a = fminf(a, rmn[w]); c = fmaxf(c, rmx[w]); }
        int b = img / 3;                // img = b*3 + channel
        atomicMin(&g_mn[b], __float_as_uint(a));
        atomicMax(&g_mx[b], __float_as_uint(c));
    }

    // antialiased triangle resize along kys, for column and its mirror
    if (tid < OUT_HW) {
        int kxs1 = (kx + 512) & (N - 1);    // fftshift along kx  (covers 512..1023, 0)
        int kxs2 = 512 - kx;                // mirror column       (covers 0..512)
        float sf = ((float)tid + 0.5f) * (1024.0f/224.0f) - 0.5f;
        int i0 = max(0, (int)ceilf(sf - KRAD));
        int i1 = min(N - 1, (int)floorf(sf + KRAD));
        float acc1 = 0.0f, acc2 = 0.0f, sw = 0.0f;
        for (int i = i0; i <= i1; ++i) {
            float w = fmaxf(0.0f, 1.0f - fabsf(sf - (float)i) * KSCL);
            acc1 += w * m[i];
            acc2 += w * m[(N - i) & (N - 1)];
            sw += w;
        }
        g_T[((size_t)img * N + kxs1) * OUT_HW + tid] = acc1 / sw;
        g_T[((size_t)img * N + kxs2) * OUT_HW + tid] = acc2 / sw;
    }
}

__global__ void __launch_bounds__(224) k_resize2(float* __restrict__ out) {
    int blk = blockIdx.x;               // img*224 + ox
    int img = blk / OUT_HW;
    int ox  = blk - img * OUT_HW;
    int oy  = threadIdx.x;
    float sf = ((float)ox + 0.5f) * (1024.0f/224.0f) - 0.5f;
    int i0 = max(0, (int)ceilf(sf - KRAD));
    int i1 = min(N - 1, (int)floorf(sf + KRAD));
    float acc = 0.0f, sw = 0.0f;
    const float* base = g_T + (size_t)img * N * OUT_HW + oy;
    for (int i = i0; i <= i1; ++i) {
        float w = fmaxf(0.0f, 1.0f - fabsf(sf - (float)i) * KSCL);
        acc += w * base[(size_t)i * OUT_HW]; sw += w;
    }
    int b = img / 3;
    float mn = __uint_as_float(g_mn[b]);
    float mx = __uint_as_float(g_mx[b]);
    float v = (acc / sw - mn) / (mx - mn + 1e-8f);
    out[((size_t)img * OUT_HW + oy) * OUT_HW + ox] = v;
}

extern "C" void kernel_launch(void* const* d_in, const int* in_sizes, int n_in,
                              void* d_out, int out_size) {
    (void)in_sizes; (void)n_in; (void)out_size;
    const float* in = (const float*)d_in[0];
    float* out = (float*)d_out;

    k_init<<<1, 256>>>();
    k_rowfft<<<NIMG * (N/2), 256>>>(in);
    dim3 tg((W + 31) / 32, N / 32, NIMG), tb(32, 8);
    k_transpose<<<tg, tb>>>();
    k_colfft<<<NIMG * W, 256>>>();
    k_resize2<<<NIMG * OUT_HW, 224>>>(out);
}

// round 5
// speedup vs baseline: 3.4567x; 1.7847x over previous
#include <cuda_runtime.h>
#include <math.h>

#define NIMG 48            // B*C = 16*3
#define NBATCH 16
#define N 1024
#define OUT_HW 224
#define W 513              // kept kx columns (Hermitian half)
#define WP 520             // padded row stride for g_A (float2 units)
#define KRAD (1024.0f/224.0f)
#define KSCL (224.0f/1024.0f)

// padded shared indexing: breaks stride-4 float2 4-way bank conflicts
#define P(i) ((i) + ((i) >> 4))
#define S_SZ (N + (N >> 4))          // 1088 float2
#define TW_SZ (256 + 16)             // padded 256-entry table

// scratch (static device arrays; no allocation allowed)
__device__ float2 g_A[(size_t)NIMG * N * WP];       // row-FFT output [img][y][kx 0..512]
__device__ float2 g_B[(size_t)NIMG * W * N];        // transposed     [img][kx][y]
__device__ float  g_T[(size_t)NIMG * N * OUT_HW];   // ky-resized     [img][kxs][oy]
__device__ float2 g_tw[256];
__device__ unsigned int g_mn[NBATCH];
__device__ unsigned int g_mx[NBATCH];

__device__ __forceinline__ float2 cmul(float2 a, float2 b) {
    return make_float2(a.x*b.x - a.y*b.y, a.x*b.y + a.y*b.x);
}
__device__ __forceinline__ float2 cadd(float2 a, float2 b){ return make_float2(a.x+b.x, a.y+b.y); }
__device__ __forceinline__ float2 csub(float2 a, float2 b){ return make_float2(a.x-b.x, a.y-b.y); }

// base-4 digit reversal of an 8-bit index (256 = 4^4)
__device__ __forceinline__ int rev4_8(int u) {
    return ((u & 3) << 6) | ((u & 12) << 2) | ((u >> 2) & 12) | ((u >> 6) & 3);
}

__device__ __forceinline__ void load_tw(float2* tw, int tid) {
    tw[P(tid)] = g_tw[tid];          // 256 threads, 256 entries
}

// radix-4 DIT butterfly (no twiddle): y0..y3 from x0..x3
__device__ __forceinline__ void bfly4(float2 x0, float2 x1, float2 x2, float2 x3,
                                      float2& y0, float2& y1, float2& y2, float2& y3) {
    float2 u0 = cadd(x0, x2);
    float2 u1 = csub(x0, x2);
    float2 u2 = cadd(x1, x3);
    float2 u3 = csub(x1, x3);
    y0 = cadd(u0, u2);
    y1 = make_float2(u1.x + u3.y, u1.y - u3.x);   // u1 - i*u3
    y2 = csub(u0, u2);
    y3 = make_float2(u1.x - u3.y, u1.y + u3.x);   // u1 + i*u3
}

// stages 1..4 of the 1024-pt radix-4 DIT FFT (stage 0 done by caller in regs).
// s[] padded via P(); tw[] padded 256-entry table. 256 threads.
__device__ __forceinline__ void fft1024_r4_tail(float2* s, const float2* tw, int tid) {
    #pragma unroll
    for (int st = 1; st < 5; ++st) {
        int quarter = 1 << (2*st);
        int pos  = tid & (quarter - 1);
        int base = ((tid - pos) << 2) + pos;
        int tstep = 256 >> (2*st);           // N/len
        float2 w1 = tw[P(pos * tstep)];
        float2 x0 = s[P(base)];
        float2 x1 = s[P(base + quarter)];
        float2 x2 = s[P(base + 2*quarter)];
        float2 x3 = s[P(base + 3*quarter)];
        float2 w2 = cmul(w1, w1);
        float2 w3 = cmul(w2, w1);
        x1 = cmul(w1, x1);
        x2 = cmul(w2, x2);
        x3 = cmul(w3, x3);
        float2 y0, y1, y2, y3;
        bfly4(x0, x1, x2, x3, y0, y1, y2, y3);
        s[P(base)]             = y0;
        s[P(base + quarter)]   = y1;
        s[P(base + 2*quarter)] = y2;
        s[P(base + 3*quarter)] = y3;
        __syncthreads();
    }
}

__global__ void k_init(void) {
    int t = threadIdx.x;
    if (t < NBATCH) { g_mn[t] = 0x7f800000u; g_mx[t] = 0u; }
    float sn, cs;
    sincosf(-6.283185307179586f * (float)t / 1024.0f, &sn, &cs);
    g_tw[t] = make_float2(cs, sn);
}

// One block = two real rows (y, y+512) of one image, packed as one complex FFT.
// Stage 0 fused with the global load.
__global__ void __launch_bounds__(256) k_rowfft(const float* __restrict__ in) {
    __shared__ float2 s[S_SZ];
    __shared__ float2 tw[TW_SZ];
    int bx  = blockIdx.x;               // img*512 + ya
    int img = bx >> 9;
    int ya  = bx & 511;
    int tid = threadIdx.x;
    load_tw(tw, tid);
    const float* ra = in + ((size_t)img * N + ya) * N;
    const float* rb = ra + (size_t)512 * N;
    float2 x0 = make_float2(ra[tid],       rb[tid]);
    float2 x1 = make_float2(ra[tid + 256], rb[tid + 256]);
    float2 x2 = make_float2(ra[tid + 512], rb[tid + 512]);
    float2 x3 = make_float2(ra[tid + 768], rb[tid + 768]);
    float2 y0, y1, y2, y3;
    bfly4(x0, x1, x2, x3, y0, y1, y2, y3);
    int r4 = rev4_8(tid) << 2;
    s[P(r4 + 0)] = y0;
    s[P(r4 + 1)] = y1;
    s[P(r4 + 2)] = y2;
    s[P(r4 + 3)] = y3;
    __syncthreads();
    fft1024_r4_tail(s, tw, tid);
    // unpack the two real spectra; keep kx = 0..512 only (Hermitian half)
    float2* oa = g_A + ((size_t)img * N + ya) * WP;
    float2* ob = oa + (size_t)512 * WP;
    for (int e = tid; e < W; e += 256) {
        float2 Z  = s[P(e)];
        float2 Zm = s[P((N - e) & (N - 1))];
        oa[e] = make_float2(0.5f * (Z.x + Zm.x), 0.5f * (Z.y - Zm.y));
        ob[e] = make_float2(0.5f * (Z.y + Zm.y), 0.5f * (Zm.x - Z.x));
    }
}

__global__ void k_transpose(void) {
    __shared__ float2 tile[32][33];
    int img = blockIdx.z;
    int x0 = blockIdx.x * 32, y0 = blockIdx.y * 32;
    int tx = threadIdx.x, ty = threadIdx.y;
    if (x0 + tx < W) {
        #pragma unroll
        for (int dy = ty; dy < 32; dy += 8)
            tile[dy][tx] = g_A[((size_t)img * N + (y0 + dy)) * WP + x0 + tx];
    }
    __syncthreads();
    #pragma unroll
    for (int dy = ty; dy < 32; dy += 8)
        if (x0 + dy < W)
            g_B[((size_t)img * W + (x0 + dy)) * N + y0 + tx] = tile[tx][dy];
}

// One block = one kept column kx (0..512). Emits TWO resized g_T rows.
__global__ void __launch_bounds__(256) k_colfft(void) {
    __shared__ float2 s[S_SZ];
    __shared__ float2 tw[TW_SZ];
    __shared__ float  m[N];             // shifted log-magnitude over kys
    __shared__ float  rmn[8], rmx[8];
    int blk = blockIdx.x;               // img*513 + kx
    int img = blk / W;
    int kx  = blk - img * W;
    int tid = threadIdx.x;
    load_tw(tw, tid);
    const float2* cp = g_B + (size_t)blk * N;
    float2 x0 = cp[tid];
    float2 x1 = cp[tid + 256];
    float2 x2 = cp[tid + 512];
    float2 x3 = cp[tid + 768];
    float2 y0, y1, y2, y3;
    bfly4(x0, x1, x2, x3, y0, y1, y2, y3);
    int r4 = rev4_8(tid) << 2;
    s[P(r4 + 0)] = y0;
    s[P(r4 + 1)] = y1;
    s[P(r4 + 2)] = y2;
    s[P(r4 + 3)] = y3;
    __syncthreads();
    fft1024_r4_tail(s, tw, tid);

    float mn = 3.4e38f, mx = 0.0f;
    #pragma unroll
    for (int e = tid; e < N; e += 256) {
        float2 v = s[P(e)];
        float mag = log1pf(sqrtf(v.x*v.x + v.y*v.y));
        m[(e + 512) & (N - 1)] = mag;   // fftshift along ky
        mn = fminf(mn, mag); mx = fmaxf(mx, mag);
    }
    #pragma unroll
    for (int o = 16; o; o >>= 1) {
        mn = fminf(mn, __shfl_xor_sync(0xffffffffu, mn, o));
        mx = fmaxf(mx, __shfl_xor_sync(0xffffffffu, mx, o));
    }
    if ((tid & 31) == 0) { rmn[tid >> 5] = mn; rmx[tid >> 5] = mx; }
    __syncthreads();                    // also fences m[] for resize reads
    if (tid == 0) {
        float a = rmn[0], c = rmx[0];
        #pragma unroll
        for (int w = 1; w < 8; ++w) { a = fminf(a, rmn[w]); c = fmaxf(c, rmx[w]); }
        int b = img / 3;                // img = b*3 + channel
        atomicMin(&g_mn[b], __float_as_uint(a));
        atomicMax(&g_mx[b], __float_as_uint(c));
    }

    // antialiased triangle resize along kys, for column and its Hermitian mirror
    if (tid < OUT_HW) {
        int kxs1 = (kx + 512) & (N - 1);    // fftshift along kx  (covers 512..1023, 0)
        int kxs2 = 512 - kx;                // mirror column       (covers 0..512)
        float sf = ((float)tid + 0.5f) * (1024.0f/224.0f) - 0.5f;
        int i0 = max(0, (int)ceilf(sf - KRAD));
        int i1 = min(N - 1, (int)floorf(sf + KRAD));
        float acc1 = 0.0f, acc2 = 0.0f, sw = 0.0f;
        for (int i = i0; i <= i1; ++i) {
            float w = fmaxf(0.0f, 1.0f - fabsf(sf - (float)i) * KSCL);
            acc1 += w * m[i];
            acc2 += w * m[(N - i) & (N - 1)];
            sw += w;
        }
        g_T[((size_t)img * N + kxs1) * OUT_HW + tid] = acc1 / sw;
        g_T[((size_t)img * N + kxs2) * OUT_HW + tid] = acc2 / sw;
    }
}

__global__ void __launch_bounds__(224) k_resize2(float* __restrict__ out) {
    int blk = blockIdx.x;               // img*224 + ox
    int img = blk / OUT_HW;
    int ox  = blk - img * OUT_HW;
    int oy  = threadIdx.x;
    float sf = ((float)ox + 0.5f) * (1024.0f/224.0f) - 0.5f;
    int i0 = max(0, (int)ceilf(sf - KRAD));
    int i1 = min(N - 1, (int)floorf(sf + KRAD));
    float acc = 0.0f, sw = 0.0f;
    const float* base = g_T + (size_t)img * N * OUT_HW + oy;
    for (int i = i0; i <= i1; ++i) {
        float w = fmaxf(0.0f, 1.0f - fabsf(sf - (float)i) * KSCL);
        acc += w * base[(size_t)i * OUT_HW]; sw += w;
    }
    int b = img / 3;
    float mn = __uint_as_float(g_mn[b]);
    float mx = __uint_as_float(g_mx[b]);
    float v = (acc / sw - mn) / (mx - mn + 1e-8f);
    out[((size_t)img * OUT_HW + oy) * OUT_HW + ox] = v;
}

extern "C" void kernel_launch(void* const* d_in, const int* in_sizes, int n_in,
                              void* d_out, int out_size) {
    (void)in_sizes; (void)n_in; (void)out_size;
    const float* in = (const float*)d_in[0];
    float* out = (float*)d_out;

    k_init<<<1, 256>>>();
    k_rowfft<<<NIMG * (N/2), 256>>>(in);
    dim3 tg((W + 31) / 32, N / 32, NIMG), tb(32, 8);
    k_transpose<<<tg, tb>>>();
    k_colfft<<<NIMG * W, 256>>>();
    k_resize2<<<NIMG * OUT_HW, 224>>>(out);
}

// round 6
// speedup vs baseline: 4.7690x; 1.3796x over previous
#include <cuda_runtime.h>
#include <math.h>

#define NIMG 48            // B*C = 16*3
#define NBATCH 16
#define N 1024
#define OUT_HW 224
#define W 513              // kept kx columns (Hermitian half)
#define WP 520             // padded row stride for g_A (float2 units)
#define WB 514             // padded kx rows in g_B (2 cols per block)
#define KRAD (1024.0f/224.0f)
#define KSCL (224.0f/1024.0f)

// padded shared indexing
#define P(i)  ((i) + ((i) >> 4) + ((i) >> 8))
#define S_SZ  1092
#define PT(i) ((i) + ((i) >> 4))
#define TW_SZ 272

// scratch (static device arrays; no allocation allowed)
__device__ float2 g_A[(size_t)NIMG * N * WP];       // row-FFT output [img][y][kx 0..512]
__device__ float2 g_B[(size_t)NIMG * WB * N];       // transposed     [img][kx][y]
__device__ float  g_T[(size_t)NIMG * N * OUT_HW];   // ky-resized     [img][kxs][oy]
__device__ float2 g_tw[256];
__device__ unsigned int g_mn[NBATCH];
__device__ unsigned int g_mx[NBATCH];

__device__ __forceinline__ float2 cmul(float2 a, float2 b) {
    return make_float2(a.x*b.x - a.y*b.y, a.x*b.y + a.y*b.x);
}
__device__ __forceinline__ float2 cadd(float2 a, float2 b){ return make_float2(a.x+b.x, a.y+b.y); }
__device__ __forceinline__ float2 csub(float2 a, float2 b){ return make_float2(a.x-b.x, a.y-b.y); }

// exp(-2*pi*i*k/16), k = 0..3 (compile-time constants under unrolled loops)
__device__ __forceinline__ float2 w16(int k) {
    const float cc[4] = {1.0f, 0.92387953251128674f, 0.70710678118654752f, 0.38268343236508978f};
    const float ss[4] = {0.0f, -0.38268343236508978f, -0.70710678118654752f, -0.92387953251128674f};
    return make_float2(cc[k], ss[k]);
}

__device__ __forceinline__ void bfly4(float2 x0, float2 x1, float2 x2, float2 x3,
                                      float2& y0, float2& y1, float2& y2, float2& y3) {
    float2 u0 = cadd(x0, x2);
    float2 u1 = csub(x0, x2);
    float2 u2 = cadd(x1, x3);
    float2 u3 = csub(x1, x3);
    y0 = cadd(u0, u2);
    y1 = make_float2(u1.x + u3.y, u1.y - u3.x);   // u1 - i*u3
    y2 = csub(u0, u2);
    y3 = make_float2(u1.x - u3.y, u1.y + u3.x);   // u1 + i*u3
}

// twiddled radix-4 butterfly: w applied as w^1, w^2, w^3 to x1..x3
__device__ __forceinline__ void stage_tw(float2& a0, float2& a1, float2& a2, float2& a3, float2 w1) {
    float2 w2 = cmul(w1, w1);
    float2 w3 = cmul(w2, w1);
    float2 b1 = cmul(a1, w1), b2 = cmul(a2, w2), b3 = cmul(a3, w3);
    bfly4(a0, b1, b2, b3, a0, a1, a2, a3);
}

// base-4 digit reversal of a 6-bit index (64 = 4^3)
__device__ __forceinline__ int rev4_6(int b) {
    return ((b & 3) << 4) | (b & 12) | (b >> 4);
}

// phase 1: stages 0+1 in registers on x[j] (positions 16b+j), store to shared
__device__ __forceinline__ void fft_ph1(float2 x[16], float2* s, int b) {
    #pragma unroll
    for (int k = 0; k < 4; ++k)
        bfly4(x[4*k], x[4*k+1], x[4*k+2], x[4*k+3],
              x[4*k], x[4*k+1], x[4*k+2], x[4*k+3]);
    // stage 1, pos = j & 3, twiddle w16(pos)
    bfly4(x[0], x[4], x[8], x[12], x[0], x[4], x[8], x[12]);   // pos=0, no twiddle
    #pragma unroll
    for (int pos = 1; pos < 4; ++pos)
        stage_tw(x[pos], x[pos+4], x[pos+8], x[pos+12], w16(pos));
    int base = 16 * b;
    #pragma unroll
    for (int j = 0; j < 16; ++j)
        s[P(base + j)] = x[j];
}

// phase 2: stages 2+3 in registers (positions c + 16*q2 + 64*q3 + 256*hi)
__device__ __forceinline__ void fft_ph2(float2* s, const float2* tw, int L) {
    int c = L & 15, hi = L >> 4;
    float2 x[16];
    #pragma unroll
    for (int q3 = 0; q3 < 4; ++q3)
        #pragma unroll
        for (int q2 = 0; q2 < 4; ++q2)
            x[q2 + 4*q3] = s[P(c + 16*q2 + 64*q3 + 256*hi)];
    float2 w16c = tw[PT(16*c)];
    #pragma unroll
    for (int q3 = 0; q3 < 4; ++q3)
        stage_tw(x[4*q3], x[4*q3+1], x[4*q3+2], x[4*q3+3], w16c);
    float2 tw4c = tw[PT(4*c)];
    #pragma unroll
    for (int q2 = 0; q2 < 4; ++q2) {
        float2 w = (q2 == 0) ? tw4c : cmul(tw4c, w16(q2));
        stage_tw(x[q2], x[q2+4], x[q2+8], x[q2+12], w);
    }
    #pragma unroll
    for (int q3 = 0; q3 < 4; ++q3)
        #pragma unroll
        for (int q2 = 0; q2 < 4; ++q2)
            s[P(c + 16*q2 + 64*q3 + 256*hi)] = x[q2 + 4*q3];
}

// phase 3: stage 4; final values in x[k + 4q] = DFT[4L+k + 256q] (natural order)
__device__ __forceinline__ void fft_ph3(float2* s, const float2* tw, int L, float2 x[16]) {
    #pragma unroll
    for (int k = 0; k < 4; ++k) {
        int pos = 4*L + k;
        float2 x0 = s[P(pos)];
        float2 x1 = s[P(pos + 256)];
        float2 x2 = s[P(pos + 512)];
        float2 x3 = s[P(pos + 768)];
        stage_tw(x0, x1, x2, x3, tw[PT(pos)]);
        x[k] = x0; x[k+4] = x1; x[k+8] = x2; x[k+12] = x3;
    }
}

__global__ void k_init(void) {
    int t = threadIdx.x;
    if (t < NBATCH) { g_mn[t] = 0x7f800000u; g_mx[t] = 0u; }
    float sn, cs;
    sincosf(-6.283185307179586f * (float)t / 1024.0f, &sn, &cs);
    g_tw[t] = make_float2(cs, sn);
}

// One FFT = two real rows (y, y+512) packed complex. 2 FFTs per 128-thread block.
__global__ void __launch_bounds__(128) k_rowfft(const float* __restrict__ in) {
    __shared__ float2 s[2][S_SZ];
    __shared__ float2 tw[TW_SZ];
    int T = threadIdx.x, f = T >> 6, L = T & 63;
    #pragma unroll
    for (int j = T; j < 256; j += 128) tw[PT(j)] = g_tw[j];
    int bx  = blockIdx.x;               // img*256 + pg
    int img = bx >> 8;
    int ya  = ((bx & 255) << 1) + f;
    __syncthreads();                    // tw ready

    const float* ra = in + ((size_t)img * N + ya) * N;
    const float* rb = ra + (size_t)512 * N;
    float2 x[16];
    int rb6 = rev4_6(L);
    #pragma unroll
    for (int j = 0; j < 16; ++j) {
        int gi = rb6 + 64*((j >> 2) & 3) + 256*(j & 3);
        x[j] = make_float2(ra[gi], rb[gi]);
    }
    fft_ph1(x, s[f], L);
    __syncthreads();
    fft_ph2(s[f], tw, L);
    __syncthreads();
    fft_ph3(s[f], tw, L, x);
    // phase-3 read/write sets are per-thread disjoint: store without extra sync
    #pragma unroll
    for (int k = 0; k < 4; ++k)
        #pragma unroll
        for (int q = 0; q < 4; ++q)
            s[f][P(4*L + k + 256*q)] = x[k + 4*q];
    __syncthreads();

    // Hermitian unpack; keep kx = 0..512
    float2* oa = g_A + ((size_t)img * N + ya) * WP;
    float2* ob = oa + (size_t)512 * WP;
    for (int e = L; e < W; e += 64) {
        float2 Z  = s[f][P(e)];
        float2 Zm = s[f][P((N - e) & (N - 1))];
        oa[e] = make_float2(0.5f * (Z.x + Zm.x), 0.5f * (Z.y - Zm.y));
        ob[e] = make_float2(0.5f * (Z.y + Zm.y), 0.5f * (Zm.x - Z.x));
    }
}

__global__ void k_transpose(void) {
    __shared__ float2 tile[32][33];
    int img = blockIdx.z;
    int x0 = blockIdx.x * 32, y0 = blockIdx.y * 32;
    int tx = threadIdx.x, ty = threadIdx.y;
    if (x0 + tx < W) {
        #pragma unroll
        for (int dy = ty; dy < 32; dy += 8)
            tile[dy][tx] = g_A[((size_t)img * N + (y0 + dy)) * WP + x0 + tx];
    }
    __syncthreads();
    #pragma unroll
    for (int dy = ty; dy < 32; dy += 8)
        if (x0 + dy < W)
            g_B[((size_t)img * WB + (x0 + dy)) * N + y0 + tx] = tile[tx][dy];
}

// One FFT = one kept column kx. 2 columns per 128-thread block.
__global__ void __launch_bounds__(128) k_colfft(void) {
    __shared__ float2 s[2][S_SZ];
    __shared__ float2 tw[TW_SZ];
    __shared__ float  m[2][N];          // shifted log-magnitudes
    __shared__ float  red[8];           // 4 warps: min[0..3], max[4..7]
    int T = threadIdx.x, f = T >> 6, L = T & 63;
    #pragma unroll
    for (int j = T; j < 256; j += 128) tw[PT(j)] = g_tw[j];
    int bx  = blockIdx.x;               // img*257 + cg
    int img = bx / 257;
    int cg  = bx - img * 257;
    int kx  = 2*cg + f;                 // 0..513 (513 is padding, zeros)
    bool valid = (kx < W);
    __syncthreads();                    // tw ready

    const float2* cp = g_B + ((size_t)img * WB + kx) * N;
    float2 x[16];
    int rb6 = rev4_6(L);
    #pragma unroll
    for (int j = 0; j < 16; ++j)
        x[j] = cp[rb6 + 64*((j >> 2) & 3) + 256*(j & 3)];
    fft_ph1(x, s[f], L);
    __syncthreads();
    fft_ph2(s[f], tw, L);
    __syncthreads();
    fft_ph3(s[f], tw, L, x);

    // log-magnitude straight from registers; fftshift along ky
    float mn = 3.4e38f, mx = 0.0f;
    #pragma unroll
    for (int k = 0; k < 4; ++k)
        #pragma unroll
        for (int q = 0; q < 4; ++q) {
            int n0 = 4*L + k + 256*q;
            float2 v = x[k + 4*q];
            float mag = log1pf(sqrtf(v.x*v.x + v.y*v.y));
            m[f][(n0 + 512) & (N - 1)] = mag;
            mn = fminf(mn, mag); mx = fmaxf(mx, mag);
        }
    #pragma unroll
    for (int o = 16; o; o >>= 1) {
        mn = fminf(mn, __shfl_xor_sync(0xffffffffu, mn, o));
        mx = fmaxf(mx, __shfl_xor_sync(0xffffffffu, mx, o));
    }
    int wid = T >> 5;                   // 0..3; warps 2f, 2f+1 belong to FFT f
    if ((T & 31) == 0) { red[wid] = mn; red[4 + wid] = mx; }
    __syncthreads();                    // red + m[] ready
    if (L == 0 && valid) {
        float a  = fminf(red[2*f], red[2*f + 1]);
        float c2 = fmaxf(red[4 + 2*f], red[4 + 2*f + 1]);
        int b = img / 3;                // img = batch*3 + channel
        atomicMin(&g_mn[b], __float_as_uint(a));
        atomicMax(&g_mx[b], __float_as_uint(c2));
    }

    // antialiased triangle resize along kys, for column and its Hermitian mirror
    if (valid) {
        int kxs1 = (kx + 512) & (N - 1);    // fftshift along kx (covers 512..1023, 0)
        int kxs2 = 512 - kx;                // mirror column      (covers 0..512)
        float* gt1 = g_T + ((size_t)img * N + kxs1) * OUT_HW;
        float* gt2 = g_T + ((size_t)img * N + kxs2) * OUT_HW;
        for (int oy = L; oy < OUT_HW; oy += 64) {
            float sf = ((float)oy + 0.5f) * (1024.0f/224.0f) - 0.5f;
            int i0 = max(0, (int)ceilf(sf - KRAD));
            int i1 = min(N - 1, (int)floorf(sf + KRAD));
            float acc1 = 0.0f, acc2 = 0.0f, sw = 0.0f;
            for (int i = i0; i <= i1; ++i) {
                float w = fmaxf(0.0f, 1.0f - fabsf(sf - (float)i) * KSCL);
                acc1 += w * m[f][i];
                acc2 += w * m[f][(N - i) & (N - 1)];
                sw += w;
            }
            gt1[oy] = acc1 / sw;
            gt2[oy] = acc2 / sw;
        }
    }
}

__global__ void __launch_bounds__(224) k_resize2(float* __restrict__ out) {
    int blk = blockIdx.x;               // img*224 + ox
    int img = blk / OUT_HW;
    int ox  = blk - img * OUT_HW;
    int oy  = threadIdx.x;
    float sf = ((float)ox + 0.5f) * (1024.0f/224.0f) - 0.5f;
    int i0 = max(0, (int)ceilf(sf - KRAD));
    int i1 = min(N - 1, (int)floorf(sf + KRAD));
    float acc = 0.0f, sw = 0.0f;
    const float* base = g_T + (size_t)img * N * OUT_HW + oy;
    for (int i = i0; i <= i1; ++i) {
        float w = fmaxf(0.0f, 1.0f - fabsf(sf - (float)i) * KSCL);
        acc += w * base[(size_t)i * OUT_HW]; sw += w;
    }
    int b = img / 3;
    float mn = __uint_as_float(g_mn[b]);
    float mx = __uint_as_float(g_mx[b]);
    float v = (acc / sw - mn) / (mx - mn + 1e-8f);
    out[((size_t)img * OUT_HW + oy) * OUT_HW + ox] = v;
}

extern "C" void kernel_launch(void* const* d_in, const int* in_sizes, int n_in,
                              void* d_out, int out_size) {
    (void)in_sizes; (void)n_in; (void)out_size;
    const float* in = (const float*)d_in[0];
    float* out = (float*)d_out;

    k_init<<<1, 256>>>();
    k_rowfft<<<NIMG * 256, 128>>>(in);
    dim3 tg((W + 31) / 32, N / 32, NIMG), tb(32, 8);
    k_transpose<<<tg, tb>>>();
    k_colfft<<<NIMG * 257, 128>>>();
    k_resize2<<<NIMG * OUT_HW, 224>>>(out);
}

// round 7
// speedup vs baseline: 5.1441x; 1.0787x over previous
#include <cuda_runtime.h>
#include <math.h>

#define NIMG 48            // B*C = 16*3
#define NBATCH 16
#define N 1024
#define OUT_HW 224
#define W 513              // kept kx columns (Hermitian half)
#define WB 514             // padded kx rows in g_B (2 cols per colfft block)
#define KRAD (1024.0f/224.0f)
#define KSCL (224.0f/1024.0f)

// padded shared indexing
#define P(i)  ((i) + ((i) >> 4) + ((i) >> 8))
#define S_SZ  1092
#define PT(i) ((i) + ((i) >> 4))
#define TW_SZ 272

// scratch (static device arrays; no allocation allowed)
__device__ float2 g_B[(size_t)NIMG * WB * N];       // column-major spectra [img][kx][y]
__device__ float  g_T[(size_t)NIMG * N * OUT_HW];   // ky-resized [img][kxs][oy]
__device__ float2 g_tw[256];
__device__ unsigned int g_mn[NBATCH];
__device__ unsigned int g_mx[NBATCH];

__device__ __forceinline__ float2 cmul(float2 a, float2 b) {
    return make_float2(a.x*b.x - a.y*b.y, a.x*b.y + a.y*b.x);
}
__device__ __forceinline__ float2 cadd(float2 a, float2 b){ return make_float2(a.x+b.x, a.y+b.y); }
__device__ __forceinline__ float2 csub(float2 a, float2 b){ return make_float2(a.x-b.x, a.y-b.y); }

// exp(-2*pi*i*k/16), k = 0..3 (compile-time constants under unrolled loops)
__device__ __forceinline__ float2 w16(int k) {
    const float cc[4] = {1.0f, 0.92387953251128674f, 0.70710678118654752f, 0.38268343236508978f};
    const float ss[4] = {0.0f, -0.38268343236508978f, -0.70710678118654752f, -0.92387953251128674f};
    return make_float2(cc[k], ss[k]);
}

__device__ __forceinline__ void bfly4(float2 x0, float2 x1, float2 x2, float2 x3,
                                      float2& y0, float2& y1, float2& y2, float2& y3) {
    float2 u0 = cadd(x0, x2);
    float2 u1 = csub(x0, x2);
    float2 u2 = cadd(x1, x3);
    float2 u3 = csub(x1, x3);
    y0 = cadd(u0, u2);
    y1 = make_float2(u1.x + u3.y, u1.y - u3.x);   // u1 - i*u3
    y2 = csub(u0, u2);
    y3 = make_float2(u1.x - u3.y, u1.y + u3.x);   // u1 + i*u3
}

__device__ __forceinline__ void stage_tw(float2& a0, float2& a1, float2& a2, float2& a3, float2 w1) {
    float2 w2 = cmul(w1, w1);
    float2 w3 = cmul(w2, w1);
    float2 b1 = cmul(a1, w1), b2 = cmul(a2, w2), b3 = cmul(a3, w3);
    bfly4(a0, b1, b2, b3, a0, a1, a2, a3);
}

// base-4 digit reversal of a 6-bit index (64 = 4^3)
__device__ __forceinline__ int rev4_6(int b) {
    return ((b & 3) << 4) | (b & 12) | (b >> 4);
}

// phase 1: stages 0+1 in registers on x[j] (positions 16b+j), store to shared
__device__ __forceinline__ void fft_ph1(float2 x[16], float2* s, int b) {
    #pragma unroll
    for (int k = 0; k < 4; ++k)
        bfly4(x[4*k], x[4*k+1], x[4*k+2], x[4*k+3],
              x[4*k], x[4*k+1], x[4*k+2], x[4*k+3]);
    bfly4(x[0], x[4], x[8], x[12], x[0], x[4], x[8], x[12]);   // pos=0, no twiddle
    #pragma unroll
    for (int pos = 1; pos < 4; ++pos)
        stage_tw(x[pos], x[pos+4], x[pos+8], x[pos+12], w16(pos));
    int base = 16 * b;
    #pragma unroll
    for (int j = 0; j < 16; ++j)
        s[P(base + j)] = x[j];
}

// phase 2: stages 2+3 in registers (positions c + 16*q2 + 64*q3 + 256*hi)
__device__ __forceinline__ void fft_ph2(float2* s, const float2* tw, int L) {
    int c = L & 15, hi = L >> 4;
    float2 x[16];
    #pragma unroll
    for (int q3 = 0; q3 < 4; ++q3)
        #pragma unroll
        for (int q2 = 0; q2 < 4; ++q2)
            x[q2 + 4*q3] = s[P(c + 16*q2 + 64*q3 + 256*hi)];
    float2 w16c = tw[PT(16*c)];
    #pragma unroll
    for (int q3 = 0; q3 < 4; ++q3)
        stage_tw(x[4*q3], x[4*q3+1], x[4*q3+2], x[4*q3+3], w16c);
    float2 tw4c = tw[PT(4*c)];
    #pragma unroll
    for (int q2 = 0; q2 < 4; ++q2) {
        float2 w = (q2 == 0) ? tw4c : cmul(tw4c, w16(q2));
        stage_tw(x[q2], x[q2+4], x[q2+8], x[q2+12], w);
    }
    #pragma unroll
    for (int q3 = 0; q3 < 4; ++q3)
        #pragma unroll
        for (int q2 = 0; q2 < 4; ++q2)
            s[P(c + 16*q2 + 64*q3 + 256*hi)] = x[q2 + 4*q3];
}

// phase 3: stage 4; final values in x[k + 4q] = DFT[4L+k + 256q] (natural order)
__device__ __forceinline__ void fft_ph3(float2* s, const float2* tw, int L, float2 x[16]) {
    #pragma unroll
    for (int k = 0; k < 4; ++k) {
        int pos = 4*L + k;
        float2 x0 = s[P(pos)];
        float2 x1 = s[P(pos + 256)];
        float2 x2 = s[P(pos + 512)];
        float2 x3 = s[P(pos + 768)];
        stage_tw(x0, x1, x2, x3, tw[PT(pos)]);
        x[k] = x0; x[k+4] = x1; x[k+8] = x2; x[k+12] = x3;
    }
}

__global__ void k_init(void) {
    int t = threadIdx.x;
    if (t < NBATCH) { g_mn[t] = 0x7f800000u; g_mx[t] = 0u; }
    float sn, cs;
    sincosf(-6.283185307179586f * (float)t / 1024.0f, &sn, &cs);
    g_tw[t] = make_float2(cs, sn);
}

// 4 FFTs per 256-thread block; each FFT = two real rows (ya, ya+512) packed.
// Hermitian unpack writes DIRECTLY in transposed order: for each kx, the 4
// consecutive-row values form one 32B chunk -> g_B[img][kx][4rg..4rg+4).
__global__ void __launch_bounds__(256) k_rowfft(const float* __restrict__ in) {
    __shared__ float2 s[4][S_SZ];
    __shared__ float2 tw[TW_SZ];
    int T = threadIdx.x, f = T >> 6, L = T & 63;
    if (T < 256) tw[PT(T)] = g_tw[T];
    int bx  = blockIdx.x;               // img*128 + rg
    int img = bx >> 7;
    int rg  = bx & 127;
    int ya  = 4*rg + f;                 // rows 4rg..4rg+3 (+512 partners)
    __syncthreads();                    // tw ready

    const float* ra = in + ((size_t)img * N + ya) * N;
    const float* rb = ra + (size_t)512 * N;
    float2 x[16];
    int rb6 = rev4_6(L);
    #pragma unroll
    for (int j = 0; j < 16; ++j) {
        int gi = rb6 + 64*((j >> 2) & 3) + 256*(j & 3);
        x[j] = make_float2(ra[gi], rb[gi]);
    }
    fft_ph1(x, s[f], L);
    __syncthreads();
    fft_ph2(s[f], tw, L);
    __syncthreads();
    fft_ph3(s[f], tw, L, x);
    #pragma unroll
    for (int k = 0; k < 4; ++k)
        #pragma unroll
        for (int q = 0; q < 4; ++q)
            s[f][P(4*L + k + 256*q)] = x[k + 4*q];
    __syncthreads();                    // all 4 FFTs resident

    // transposed Hermitian unpack: keep kx = 0..512
    int ybase = 4 * rg;
    for (int e = T; e < W; e += 256) {
        float2 va[4], vb[4];
        #pragma unroll
        for (int g = 0; g < 4; ++g) {
            float2 Z  = s[g][P(e)];
            float2 Zm = s[g][P((N - e) & (N - 1))];
            va[g] = make_float2(0.5f * (Z.x + Zm.x), 0.5f * (Z.y - Zm.y));
            vb[g] = make_float2(0.5f * (Z.y + Zm.y), 0.5f * (Zm.x - Z.x));
        }
        float2* pa = g_B + ((size_t)img * WB + e) * N + ybase;
        float2* pb = pa + 512;
        *reinterpret_cast<float4*>(pa)     = make_float4(va[0].x, va[0].y, va[1].x, va[1].y);
        *reinterpret_cast<float4*>(pa + 2) = make_float4(va[2].x, va[2].y, va[3].x, va[3].y);
        *reinterpret_cast<float4*>(pb)     = make_float4(vb[0].x, vb[0].y, vb[1].x, vb[1].y);
        *reinterpret_cast<float4*>(pb + 2) = make_float4(vb[2].x, vb[2].y, vb[3].x, vb[3].y);
    }
}

// One FFT = one kept column kx. 2 columns per 128-thread block.
__global__ void __launch_bounds__(128) k_colfft(void) {
    __shared__ float2 s[2][S_SZ];
    __shared__ float2 tw[TW_SZ];
    __shared__ float  m[2][N];          // shifted log-magnitudes
    __shared__ float  red[8];           // 4 warps: min[0..3], max[4..7]
    int T = threadIdx.x, f = T >> 6, L = T & 63;
    #pragma unroll
    for (int j = T; j < 256; j += 128) tw[PT(j)] = g_tw[j];
    int bx  = blockIdx.x;               // img*257 + cg
    int img = bx / 257;
    int cg  = bx - img * 257;
    int kx  = 2*cg + f;                 // 0..513 (513 is padding)
    bool valid = (kx < W);
    __syncthreads();                    // tw ready

    const float2* cp = g_B + ((size_t)img * WB + kx) * N;
    float2 x[16];
    int rb6 = rev4_6(L);
    #pragma unroll
    for (int j = 0; j < 16; ++j)
        x[j] = cp[rb6 + 64*((j >> 2) & 3) + 256*(j & 3)];
    fft_ph1(x, s[f], L);
    __syncthreads();
    fft_ph2(s[f], tw, L);
    __syncthreads();
    fft_ph3(s[f], tw, L, x);

    // log-magnitude straight from registers; fftshift along ky
    float mn = 3.4e38f, mx = 0.0f;
    #pragma unroll
    for (int k = 0; k < 4; ++k)
        #pragma unroll
        for (int q = 0; q < 4; ++q) {
            int n0 = 4*L + k + 256*q;
            float2 v = x[k + 4*q];
            float mag = log1pf(sqrtf(v.x*v.x + v.y*v.y));
            m[f][(n0 + 512) & (N - 1)] = mag;
            mn = fminf(mn, mag); mx = fmaxf(mx, mag);
        }
    #pragma unroll
    for (int o = 16; o; o >>= 1) {
        mn = fminf(mn, __shfl_xor_sync(0xffffffffu, mn, o));
        mx = fmaxf(mx, __shfl_xor_sync(0xffffffffu, mx, o));
    }
    int wid = T >> 5;                   // warps 2f, 2f+1 belong to FFT f
    if ((T & 31) == 0) { red[wid] = mn; red[4 + wid] = mx; }
    __syncthreads();                    // red + m[] ready
    if (L == 0 && valid) {
        float a  = fminf(red[2*f], red[2*f + 1]);
        float c2 = fmaxf(red[4 + 2*f], red[4 + 2*f + 1]);
        int b = img / 3;                // img = batch*3 + channel
        atomicMin(&g_mn[b], __float_as_uint(a));
        atomicMax(&g_mx[b], __float_as_uint(c2));
    }

    // antialiased triangle resize along kys (incremental ramp weights),
    // for the column and its Hermitian mirror
    if (valid) {
        int kxs1 = (kx + 512) & (N - 1);
        int kxs2 = 512 - kx;
        float* gt1 = g_T + ((size_t)img * N + kxs1) * OUT_HW;
        float* gt2 = g_T + ((size_t)img * N + kxs2) * OUT_HW;
        for (int oy = L; oy < OUT_HW; oy += 64) {
            float sf = ((float)oy + 0.5f) * (1024.0f/224.0f) - 0.5f;
            int i0 = max(0, (int)ceilf(sf - KRAD));
            int i1 = min(N - 1, (int)floorf(sf + KRAD));
            int ip = (int)floorf(sf);   // i0 <= ip <= i1 always holds here
            float acc1 = 0.0f, acc2 = 0.0f, sw = 0.0f;
            float w = 1.0f - (sf - (float)i0) * KSCL;
            int i = i0;
            for (; i <= ip; ++i) {      // ascending side of the triangle
                acc1 += w * m[f][i];
                acc2 += w * m[f][(N - i) & (N - 1)];
                sw += w; w += KSCL;
            }
            w = 1.0f - ((float)i - sf) * KSCL;
            for (; i <= i1; ++i) {      // descending side
                acc1 += w * m[f][i];
                acc2 += w * m[f][(N - i) & (N - 1)];
                sw += w; w -= KSCL;
            }
            float inv = 1.0f / sw;
            gt1[oy] = acc1 * inv;
            gt2[oy] = acc2 * inv;
        }
    }
}

__global__ void __launch_bounds__(224) k_resize2(float* __restrict__ out) {
    int blk = blockIdx.x;               // img*224 + ox
    int img = blk / OUT_HW;
    int ox  = blk - img * OUT_HW;
    int oy  = threadIdx.x;
    float sf = ((float)ox + 0.5f) * (1024.0f/224.0f) - 0.5f;
    int i0 = max(0, (int)ceilf(sf - KRAD));
    int i1 = min(N - 1, (int)floorf(sf + KRAD));
    int ip = (int)floorf(sf);
    float acc = 0.0f, sw = 0.0f;
    const float* base = g_T + (size_t)img * N * OUT_HW + oy;
    float w = 1.0f - (sf - (float)i0) * KSCL;
    int i = i0;
    for (; i <= ip; ++i) { acc += w * base[(size_t)i * OUT_HW]; sw += w; w += KSCL; }
    w = 1.0f - ((float)i - sf) * KSCL;
    for (; i <= i1; ++i) { acc += w * base[(size_t)i * OUT_HW]; sw += w; w -= KSCL; }
    int b = img / 3;
    float mn = __uint_as_float(g_mn[b]);
    float mx = __uint_as_float(g_mx[b]);
    float v = (acc / sw - mn) / (mx - mn + 1e-8f);
    out[((size_t)img * OUT_HW + oy) * OUT_HW + ox] = v;
}

extern "C" void kernel_launch(void* const* d_in, const int* in_sizes, int n_in,
                              void* d_out, int out_size) {
    (void)in_sizes; (void)n_in; (void)out_size;
    const float* in = (const float*)d_in[0];
    float* out = (float*)d_out;

    k_init<<<1, 256>>>();
    k_rowfft<<<NIMG * 128, 256>>>(in);
    k_colfft<<<NIMG * 257, 128>>>();
    k_resize2<<<NIMG * OUT_HW, 224>>>(out);
}

// round 8
// speedup vs baseline: 5.2293x; 1.0165x over previous
#include <cuda_runtime.h>
#include <math.h>

#define NIMG 48            // B*C = 16*3
#define NBATCH 16
#define N 1024
#define OUT_HW 224
#define W 513              // kept kx columns (Hermitian half)
#define WB 514             // padded kx rows in g_B
#define KRAD (1024.0f/224.0f)
#define KSCL (224.0f/1024.0f)

// padded shared indexing (generic form, used only in the Hermitian unpack)
#define P(i)  ((i) + ((i) >> 4) + ((i) >> 8))
#define S_SZ  1092
#define TW_SZ 272

typedef unsigned long long u64;

// scratch (static device arrays; no allocation allowed)
__device__ u64   g_B[(size_t)NIMG * WB * N];        // column-major spectra [img][kx][y]
__device__ float g_T[(size_t)NIMG * N * OUT_HW];    // ky-resized [img][kxs][oy]
__device__ u64   g_tw[256];
__device__ unsigned int g_mn[NBATCH];
__device__ unsigned int g_mx[NBATCH];

// ---------- packed f32x2 complex primitives ----------
__device__ __forceinline__ u64 pk(float x, float y) {
    u64 r; asm("mov.b64 %0, {%1,%2};" : "=l"(r) : "f"(x), "f"(y)); return r;
}
__device__ __forceinline__ void upk(u64 a, float& x, float& y) {
    asm("mov.b64 {%0,%1}, %2;" : "=f"(x), "=f"(y) : "l"(a));
}
__device__ __forceinline__ u64 vadd(u64 a, u64 b) {
    u64 r; asm("add.rn.f32x2 %0, %1, %2;" : "=l"(r) : "l"(a), "l"(b)); return r;
}
__device__ __forceinline__ u64 vfma(u64 a, u64 b, u64 c) {
    u64 r; asm("fma.rn.f32x2 %0, %1, %2, %3;" : "=l"(r) : "l"(a), "l"(b), "l"(c)); return r;
}
#define K_NEG1 0xBF800000BF800000ULL   // (-1,-1)
#define K_PM1  0xBF8000003F800000ULL   // lo:+1, hi:-1
#define K_MP1  0x3F800000BF800000ULL   // lo:-1, hi:+1
__device__ __forceinline__ u64 vsub(u64 a, u64 b) { return vfma(b, K_NEG1, a); }  // a-b

// scalar complex multiply on packed values
__device__ __forceinline__ u64 cmul(u64 a, u64 b) {
    float ax, ay, bx, by; upk(a, ax, ay); upk(b, bx, by);
    return pk(ax*bx - ay*by, ax*by + ay*bx);
}
__device__ __forceinline__ u64 cmulc(u64 a, float bx, float by) {
    float ax, ay; upk(a, ax, ay);
    return pk(ax*bx - ay*by, ax*by + ay*bx);
}

// packed radix-4 DIT butterfly, in place
__device__ __forceinline__ void bfly4p(u64& x0, u64& x1, u64& x2, u64& x3) {
    u64 u0 = vadd(x0, x2);
    u64 u1 = vsub(x0, x2);
    u64 u2 = vadd(x1, x3);
    u64 u3 = vsub(x1, x3);
    x0 = vadd(u0, u2);
    x2 = vsub(u0, u2);
    float ux, uy; upk(u3, ux, uy);
    u64 sw = pk(uy, ux);
    x1 = vfma(sw, K_PM1, u1);   // (u1.x + u3.y, u1.y - u3.x)
    x3 = vfma(sw, K_MP1, u1);   // (u1.x - u3.y, u1.y + u3.x)
}

// butterfly with precomputed twiddle powers
__device__ __forceinline__ void stage3(u64& a0, u64& a1, u64& a2, u64& a3,
                                       u64 w1, u64 w2, u64 w3) {
    a1 = cmul(a1, w1); a2 = cmul(a2, w2); a3 = cmul(a3, w3);
    bfly4p(a0, a1, a2, a3);
}

// base-4 digit reversal of a 6-bit index (64 = 4^3)
__device__ __forceinline__ int rev4_6(int b) {
    return ((b & 3) << 4) | (b & 12) | (b >> 4);
}

// ---------- FFT phases (1024 pts, 64 threads/FFT, 16 pts/thread) ----------
// phase 1: stages 0+1 in registers, store to shared at affine offsets.
__device__ __forceinline__ void fft_ph1(u64 x[16], u64* s, int b) {
    #pragma unroll
    for (int k = 0; k < 4; ++k) bfly4p(x[4*k], x[4*k+1], x[4*k+2], x[4*k+3]);
    bfly4p(x[0], x[4], x[8], x[12]);                       // pos=0: no twiddle
    x[5]  = cmulc(x[5],   0.92387953f, -0.38268343f);      // pos=1: w, w^2, w^3
    x[9]  = cmulc(x[9],   0.70710678f, -0.70710678f);
    x[13] = cmulc(x[13],  0.38268343f, -0.92387953f);
    bfly4p(x[1], x[5], x[9], x[13]);
    x[6]  = cmulc(x[6],   0.70710678f, -0.70710678f);      // pos=2
    x[10] = cmulc(x[10],  0.0f,        -1.0f);
    x[14] = cmulc(x[14], -0.70710678f, -0.70710678f);
    bfly4p(x[2], x[6], x[10], x[14]);
    x[7]  = cmulc(x[7],   0.38268343f, -0.92387953f);      // pos=3
    x[11] = cmulc(x[11], -0.70710678f, -0.70710678f);
    x[15] = cmulc(x[15], -0.92387953f,  0.38268343f);
    bfly4p(x[3], x[7], x[11], x[15]);
    int b17 = 17*b + (b >> 4);          // == P(16b + j) - j
    #pragma unroll
    for (int j = 0; j < 16; ++j) s[b17 + j] = x[j];
}

// phase 2: stages 2+3 in registers. P(c+16q2+64q3+256hi) = (c+273hi)+17q2+68q3
__device__ __forceinline__ void fft_ph2(u64* s, const u64* tw, int L) {
    int c = L & 15, hi = L >> 4;
    int base = c + 273*hi;
    u64 x[16];
    #pragma unroll
    for (int q3 = 0; q3 < 4; ++q3)
        #pragma unroll
        for (int q2 = 0; q2 < 4; ++q2)
            x[q2 + 4*q3] = s[base + 17*q2 + 68*q3];
    u64 w1 = tw[17*c];                  // PT(16c) = 17c
    u64 w2 = cmul(w1, w1);
    u64 w3 = cmul(w2, w1);
    #pragma unroll
    for (int q3 = 0; q3 < 4; ++q3)
        stage3(x[4*q3], x[4*q3+1], x[4*q3+2], x[4*q3+3], w1, w2, w3);
    u64 v1 = tw[4*c + (c >> 2)];        // PT(4c)
    const float wc[4] = {1.0f, 0.92387953f, 0.70710678f, 0.38268343f};
    const float ws[4] = {0.0f, -0.38268343f, -0.70710678f, -0.92387953f};
    #pragma unroll
    for (int q2 = 0; q2 < 4; ++q2) {
        u64 w = (q2 == 0) ? v1 : cmulc(v1, wc[q2], ws[q2]);
        u64 ww2 = cmul(w, w);
        u64 ww3 = cmul(ww2, w);
        stage3(x[q2], x[q2+4], x[q2+8], x[q2+12], w, ww2, ww3);
    }
    #pragma unroll
    for (int q3 = 0; q3 < 4; ++q3)
        #pragma unroll
        for (int q2 = 0; q2 < 4; ++q2)
            s[base + 17*q2 + 68*q3] = x[q2 + 4*q3];
}

// phase 3: stage 4. P(4L+k+256q) = (4L+(L>>2)) + k + 273q; tw index = base+k.
// Result: x[k+4q] = DFT[4L+k+256q] (natural order).
__device__ __forceinline__ void fft_ph3(u64* s, const u64* tw, int L, u64 x[16]) {
    int base = 4*L + (L >> 2);
    #pragma unroll
    for (int k = 0; k < 4; ++k) {
        u64 w1 = tw[base + k];
        u64 w2 = cmul(w1, w1);
        u64 w3 = cmul(w2, w1);
        u64 a0 = s[base + k];
        u64 a1 = s[base + k + 273];
        u64 a2 = s[base + k + 546];
        u64 a3 = s[base + k + 819];
        a1 = cmul(a1, w1); a2 = cmul(a2, w2); a3 = cmul(a3, w3);
        bfly4p(a0, a1, a2, a3);
        x[k] = a0; x[k+4] = a1; x[k+8] = a2; x[k+12] = a3;
    }
}

__global__ void k_init(void) {
    int t = threadIdx.x;
    if (t < NBATCH) { g_mn[t] = 0x7f800000u; g_mx[t] = 0u; }
    float sn, cs;
    sincosf(-6.283185307179586f * (float)t / 1024.0f, &sn, &cs);
    g_tw[t] = pk(cs, sn);
}

// 4 FFTs per 256-thread block; each FFT = two real rows (ya, ya+512) packed.
// Hermitian unpack writes transposed 32B chunks directly into g_B.
__global__ void __launch_bounds__(256) k_rowfft(const float* __restrict__ in) {
    __shared__ u64 s[4][S_SZ];
    __shared__ u64 tw[TW_SZ];
    int T = threadIdx.x, f = T >> 6, L = T & 63;
    tw[T + (T >> 4)] = g_tw[T];         // PT(T)
    int bx  = blockIdx.x;               // img*128 + rg
    int img = bx >> 7;
    int rg  = bx & 127;
    int ya  = 4*rg + f;
    __syncthreads();                    // tw ready

    const float* ra = in + ((size_t)img * N + ya) * N;
    const float* rb = ra + (size_t)512 * N;
    u64 x[16];
    int rb6 = rev4_6(L);
    #pragma unroll
    for (int j = 0; j < 16; ++j) {
        int gi = rb6 + 64*((j >> 2) & 3) + 256*(j & 3);
        x[j] = pk(ra[gi], rb[gi]);
    }
    fft_ph1(x, s[f], L);
    __syncthreads();
    fft_ph2(s[f], tw, L);
    __syncthreads();
    fft_ph3(s[f], tw, L, x);
    {   // store naturally-ordered results (same addresses ph3 read: no sync needed)
        int base = 4*L + (L >> 2);
        #pragma unroll
        for (int k = 0; k < 4; ++k)
            #pragma unroll
            for (int q = 0; q < 4; ++q)
                s[f][base + k + 273*q] = x[k + 4*q];
    }
    __syncthreads();                    // all 4 FFTs resident

    // transposed Hermitian unpack: keep kx = 0..512
    int ybase = 4 * rg;
    for (int e = T; e < W; e += 256) {
        int em = (N - e) & (N - 1);
        u64 va[4], vb[4];
        #pragma unroll
        for (int g = 0; g < 4; ++g) {
            float zx, zy, mxx, mxy;
            upk(s[g][P(e)],  zx, zy);
            upk(s[g][P(em)], mxx, mxy);
            va[g] = pk(0.5f*(zx + mxx), 0.5f*(zy - mxy));
            vb[g] = pk(0.5f*(zy + mxy), 0.5f*(mxx - zx));
        }
        u64* pa = g_B + ((size_t)img * WB + e) * N + ybase;
        u64* pb = pa + 512;
        *reinterpret_cast<ulonglong2*>(pa)     = make_ulonglong2(va[0], va[1]);
        *reinterpret_cast<ulonglong2*>(pa + 2) = make_ulonglong2(va[2], va[3]);
        *reinterpret_cast<ulonglong2*>(pb)     = make_ulonglong2(vb[0], vb[1]);
        *reinterpret_cast<ulonglong2*>(pb + 2) = make_ulonglong2(vb[2], vb[3]);
    }
}

// One FFT = one kept column kx. 2 columns per 128-thread block.
__global__ void __launch_bounds__(128) k_colfft(void) {
    __shared__ u64 s[2][S_SZ];
    __shared__ u64 tw[TW_SZ];
    __shared__ float m[2][N];           // shifted log-magnitudes
    __shared__ float red[8];            // 4 warps: min[0..3], max[4..7]
    int T = threadIdx.x, f = T >> 6, L = T & 63;
    #pragma unroll
    for (int j = T; j < 256; j += 128) tw[j + (j >> 4)] = g_tw[j];
    int bx  = blockIdx.x;               // img*257 + cg
    int img = bx / 257;
    int cg  = bx - img * 257;
    int kx  = 2*cg + f;                 // 0..513 (513 is padding)
    bool valid = (kx < W);
    __syncthreads();                    // tw ready

    const u64* cp = g_B + ((size_t)img * WB + kx) * N;
    u64 x[16];
    int rb6 = rev4_6(L);
    #pragma unroll
    for (int j = 0; j < 16; ++j)
        x[j] = cp[rb6 + 64*((j >> 2) & 3) + 256*(j & 3)];
    fft_ph1(x, s[f], L);
    __syncthreads();
    fft_ph2(s[f], tw, L);
    __syncthreads();
    fft_ph3(s[f], tw, L, x);

    // log-magnitude straight from registers; fftshift along ky
    float mn = 3.4e38f, mx = 0.0f;
    int mbase = 4*L;
    #pragma unroll
    for (int k = 0; k < 4; ++k)
        #pragma unroll
        for (int q = 0; q < 4; ++q) {
            int cshift = (256*q + 512) & (N - 1);   // literal per q: 512,768,0,256
            float vx, vy; upk(x[k + 4*q], vx, vy);
            float mag = log1pf(sqrtf(vx*vx + vy*vy));
            m[f][mbase + k + cshift] = mag;
            mn = fminf(mn, mag); mx = fmaxf(mx, mag);
        }
    #pragma unroll
    for (int o = 16; o; o >>= 1) {
        mn = fminf(mn, __shfl_xor_sync(0xffffffffu, mn, o));
        mx = fmaxf(mx, __shfl_xor_sync(0xffffffffu, mx, o));
    }
    int wid = T >> 5;
    if ((T & 31) == 0) { red[wid] = mn; red[4 + wid] = mx; }
    __syncthreads();                    // red + m[] ready
    if (L == 0 && valid) {
        float a  = fminf(red[2*f], red[2*f + 1]);
        float c2 = fmaxf(red[4 + 2*f], red[4 + 2*f + 1]);
        int b = img / 3;
        atomicMin(&g_mn[b], __float_as_uint(a));
        atomicMax(&g_mx[b], __float_as_uint(c2));
    }

    // antialiased triangle resize along kys (ramp weights), column + mirror
    if (valid) {
        int kxs1 = (kx + 512) & (N - 1);
        int kxs2 = 512 - kx;
        float* gt1 = g_T + ((size_t)img * N + kxs1) * OUT_HW;
        float* gt2 = g_T + ((size_t)img * N + kxs2) * OUT_HW;
        for (int oy = L; oy < OUT_HW; oy += 64) {
            float sf = ((float)oy + 0.5f) * (1024.0f/224.0f) - 0.5f;
            int i0 = max(0, (int)ceilf(sf - KRAD));
            int i1 = min(N - 1, (int)floorf(sf + KRAD));
            int ip = (int)floorf(sf);
            float acc1 = 0.0f, acc2 = 0.0f, sw = 0.0f;
            float w = 1.0f - (sf - (float)i0) * KSCL;
            int i = i0;
            for (; i <= ip; ++i) {
                acc1 += w * m[f][i];
                acc2 += w * m[f][(N - i) & (N - 1)];
                sw += w; w += KSCL;
            }
            w = 1.0f - ((float)i - sf) * KSCL;
            for (; i <= i1; ++i) {
                acc1 += w * m[f][i];
                acc2 += w * m[f][(N - i) & (N - 1)];
                sw += w; w -= KSCL;
            }
            float inv = 1.0f / sw;
            gt1[oy] = acc1 * inv;
            gt2[oy] = acc2 * inv;
        }
    }
}

__global__ void __launch_bounds__(224) k_resize2(float* __restrict__ out) {
    int blk = blockIdx.x;               // img*224 + ox
    int img = blk / OUT_HW;
    int ox  = blk - img * OUT_HW;
    int oy  = threadIdx.x;
    float sf = ((float)ox + 0.5f) * (1024.0f/224.0f) - 0.5f;
    int i0 = max(0, (int)ceilf(sf - KRAD));
    int i1 = min(N - 1, (int)floorf(sf + KRAD));
    int ip = (int)floorf(sf);
    float acc = 0.0f, sw = 0.0f;
    const float* base = g_T + (size_t)img * N * OUT_HW + oy;
    float w = 1.0f - (sf - (float)i0) * KSCL;
    int i = i0;
    for (; i <= ip; ++i) { acc += w * base[(size_t)i * OUT_HW]; sw += w; w += KSCL; }
    w = 1.0f - ((float)i - sf) * KSCL;
    for (; i <= i1; ++i) { acc += w * base[(size_t)i * OUT_HW]; sw += w; w -= KSCL; }
    int b = img / 3;
    float mn = __uint_as_float(g_mn[b]);
    float mx = __uint_as_float(g_mx[b]);
    float v = (acc / sw - mn) / (mx - mn + 1e-8f);
    out[((size_t)img * OUT_HW + oy) * OUT_HW + ox] = v;
}

extern "C" void kernel_launch(void* const* d_in, const int* in_sizes, int n_in,
                              void* d_out, int out_size) {
    (void)in_sizes; (void)n_in; (void)out_size;
    const float* in = (const float*)d_in[0];
    float* out = (float*)d_out;

    k_init<<<1, 256>>>();
    k_rowfft<<<NIMG * 128, 256>>>(in);
    k_colfft<<<NIMG * 257, 128>>>();
    k_resize2<<<NIMG * OUT_HW, 224>>>(out);
}

// round 9
// speedup vs baseline: 5.6000x; 1.0709x over previous
#include <cuda_runtime.h>
#include <math.h>

#define NIMG 48            // B*C = 16*3
#define NBATCH 16
#define N 1024
#define OUT_HW 224
#define W 513              // kept kx columns (Hermitian half)
#define WB 514             // padded kx rows in g_B
#define KRAD (1024.0f/224.0f)
#define KSCL (224.0f/1024.0f)

// padded shared indexing (generic form, used only in the Hermitian unpack)
#define P(i)  ((i) + ((i) >> 4) + ((i) >> 8))
#define S_SZ  1092
#define TW_SZ 272

typedef unsigned long long u64;

// scratch (static device arrays; no allocation allowed)
__device__ u64   g_B[(size_t)NIMG * WB * N];        // column-major spectra [img][kx][y]
__device__ float g_T[(size_t)NIMG * N * OUT_HW];    // ky-resized [img][kxs][oy]
__device__ u64   g_tw[256];
__device__ unsigned int g_mn[NBATCH];
__device__ unsigned int g_mx[NBATCH];

// ---------- packed f32x2 complex primitives ----------
__device__ __forceinline__ u64 pk(float x, float y) {
    u64 r; asm("mov.b64 %0, {%1,%2};" : "=l"(r) : "f"(x), "f"(y)); return r;
}
__device__ __forceinline__ void upk(u64 a, float& x, float& y) {
    asm("mov.b64 {%0,%1}, %2;" : "=f"(x), "=f"(y) : "l"(a));
}
__device__ __forceinline__ u64 vadd(u64 a, u64 b) {
    u64 r; asm("add.rn.f32x2 %0, %1, %2;" : "=l"(r) : "l"(a), "l"(b)); return r;
}
__device__ __forceinline__ u64 vfma(u64 a, u64 b, u64 c) {
    u64 r; asm("fma.rn.f32x2 %0, %1, %2, %3;" : "=l"(r) : "l"(a), "l"(b), "l"(c)); return r;
}
#define K_NEG1 0xBF800000BF800000ULL   // (-1,-1)
#define K_PM1  0xBF8000003F800000ULL   // lo:+1, hi:-1
#define K_MP1  0x3F800000BF800000ULL   // lo:-1, hi:+1
__device__ __forceinline__ u64 vsub(u64 a, u64 b) { return vfma(b, K_NEG1, a); }  // a-b

// scalar complex multiply on packed values
__device__ __forceinline__ u64 cmul(u64 a, u64 b) {
    float ax, ay, bx, by; upk(a, ax, ay); upk(b, bx, by);
    return pk(ax*bx - ay*by, ax*by + ay*bx);
}
__device__ __forceinline__ u64 cmulc(u64 a, float bx, float by) {
    float ax, ay; upk(a, ax, ay);
    return pk(ax*bx - ay*by, ax*by + ay*bx);
}

// packed radix-4 DIT butterfly, in place
__device__ __forceinline__ void bfly4p(u64& x0, u64& x1, u64& x2, u64& x3) {
    u64 u0 = vadd(x0, x2);
    u64 u1 = vsub(x0, x2);
    u64 u2 = vadd(x1, x3);
    u64 u3 = vsub(x1, x3);
    x0 = vadd(u0, u2);
    x2 = vsub(u0, u2);
    float ux, uy; upk(u3, ux, uy);
    u64 sw = pk(uy, ux);
    x1 = vfma(sw, K_PM1, u1);   // (u1.x + u3.y, u1.y - u3.x)
    x3 = vfma(sw, K_MP1, u1);   // (u1.x - u3.y, u1.y + u3.x)
}

// butterfly with precomputed twiddle powers
__device__ __forceinline__ void stage3(u64& a0, u64& a1, u64& a2, u64& a3,
                                       u64 w1, u64 w2, u64 w3) {
    a1 = cmul(a1, w1); a2 = cmul(a2, w2); a3 = cmul(a3, w3);
    bfly4p(a0, a1, a2, a3);
}

// base-4 digit reversal of a 6-bit index (64 = 4^3), self-inverse
__device__ __forceinline__ int rev4_6(int b) {
    return ((b & 3) << 4) | (b & 12) | (b >> 4);
}

// ---------- FFT phases (1024 pts, 64 threads/FFT, 16 pts/thread) ----------
// phase 1: stages 0+1 in registers, store to shared at affine offsets.
// Caller passes b = butterfly-group id (thread relabeling: b = rev4_6(L) so
// the global loads for x[] are contiguous in L while the layout in s[] is
// unchanged).
__device__ __forceinline__ void fft_ph1(u64 x[16], u64* s, int b) {
    #pragma unroll
    for (int k = 0; k < 4; ++k) bfly4p(x[4*k], x[4*k+1], x[4*k+2], x[4*k+3]);
    bfly4p(x[0], x[4], x[8], x[12]);                       // pos=0: no twiddle
    x[5]  = cmulc(x[5],   0.92387953f, -0.38268343f);      // pos=1: w, w^2, w^3
    x[9]  = cmulc(x[9],   0.70710678f, -0.70710678f);
    x[13] = cmulc(x[13],  0.38268343f, -0.92387953f);
    bfly4p(x[1], x[5], x[9], x[13]);
    x[6]  = cmulc(x[6],   0.70710678f, -0.70710678f);      // pos=2
    x[10] = cmulc(x[10],  0.0f,        -1.0f);
    x[14] = cmulc(x[14], -0.70710678f, -0.70710678f);
    bfly4p(x[2], x[6], x[10], x[14]);
    x[7]  = cmulc(x[7],   0.38268343f, -0.92387953f);      // pos=3
    x[11] = cmulc(x[11], -0.70710678f, -0.70710678f);
    x[15] = cmulc(x[15], -0.92387953f,  0.38268343f);
    bfly4p(x[3], x[7], x[11], x[15]);
    int b17 = 17*b + (b >> 4);          // == P(16b + j) - j
    #pragma unroll
    for (int j = 0; j < 16; ++j) s[b17 + j] = x[j];
}

// phase 2: stages 2+3 in registers. P(c+16q2+64q3+256hi) = (c+273hi)+17q2+68q3
__device__ __forceinline__ void fft_ph2(u64* s, const u64* tw, int L) {
    int c = L & 15, hi = L >> 4;
    int base = c + 273*hi;
    u64 x[16];
    #pragma unroll
    for (int q3 = 0; q3 < 4; ++q3)
        #pragma unroll
        for (int q2 = 0; q2 < 4; ++q2)
            x[q2 + 4*q3] = s[base + 17*q2 + 68*q3];
    u64 w1 = tw[17*c];                  // PT(16c) = 17c
    u64 w2 = cmul(w1, w1);
    u64 w3 = cmul(w2, w1);
    #pragma unroll
    for (int q3 = 0; q3 < 4; ++q3)
        stage3(x[4*q3], x[4*q3+1], x[4*q3+2], x[4*q3+3], w1, w2, w3);
    u64 v1 = tw[4*c + (c >> 2)];        // PT(4c)
    const float wc[4] = {1.0f, 0.92387953f, 0.70710678f, 0.38268343f};
    const float ws[4] = {0.0f, -0.38268343f, -0.70710678f, -0.92387953f};
    #pragma unroll
    for (int q2 = 0; q2 < 4; ++q2) {
        u64 w = (q2 == 0) ? v1 : cmulc(v1, wc[q2], ws[q2]);
        u64 ww2 = cmul(w, w);
        u64 ww3 = cmul(ww2, w);
        stage3(x[q2], x[q2+4], x[q2+8], x[q2+12], w, ww2, ww3);
    }
    #pragma unroll
    for (int q3 = 0; q3 < 4; ++q3)
        #pragma unroll
        for (int q2 = 0; q2 < 4; ++q2)
            s[base + 17*q2 + 68*q3] = x[q2 + 4*q3];
}

// phase 3: stage 4. P(4L+k+256q) = (4L+(L>>2)) + k + 273q; tw index = base+k.
// Result: x[k+4q] = DFT[4L+k+256q] (natural order).
__device__ __forceinline__ void fft_ph3(u64* s, const u64* tw, int L, u64 x[16]) {
    int base = 4*L + (L >> 2);
    #pragma unroll
    for (int k = 0; k < 4; ++k) {
        u64 w1 = tw[base + k];
        u64 w2 = cmul(w1, w1);
        u64 w3 = cmul(w2, w1);
        u64 a0 = s[base + k];
        u64 a1 = s[base + k + 273];
        u64 a2 = s[base + k + 546];
        u64 a3 = s[base + k + 819];
        a1 = cmul(a1, w1); a2 = cmul(a2, w2); a3 = cmul(a3, w3);
        bfly4p(a0, a1, a2, a3);
        x[k] = a0; x[k+4] = a1; x[k+8] = a2; x[k+12] = a3;
    }
}

__global__ void k_init(void) {
    int t = threadIdx.x;
    if (t < NBATCH) { g_mn[t] = 0x7f800000u; g_mx[t] = 0u; }
    float sn, cs;
    sincosf(-6.283185307179586f * (float)t / 1024.0f, &sn, &cs);
    g_tw[t] = pk(cs, sn);
}

// 4 FFTs per 256-thread block; each FFT = two real rows (ya, ya+512) packed.
// Hermitian unpack writes transposed 32B chunks directly into g_B.
__global__ void __launch_bounds__(256) k_rowfft(const float* __restrict__ in) {
    __shared__ u64 s[4][S_SZ];
    __shared__ u64 tw[TW_SZ];
    int T = threadIdx.x, f = T >> 6, L = T & 63;
    tw[T + (T >> 4)] = g_tw[T];         // PT(T)
    int bx  = blockIdx.x;               // img*128 + rg
    int img = bx >> 7;
    int rg  = bx & 127;
    int ya  = 4*rg + f;
    __syncthreads();                    // tw ready

    const float* ra = in + ((size_t)img * N + ya) * N;
    const float* rb = ra + (size_t)512 * N;
    // relabeled: this thread runs butterfly group rev4_6(L) -> contiguous loads
    u64 x[16];
    #pragma unroll
    for (int j = 0; j < 16; ++j) {
        int gi = L + 64*((j >> 2) & 3) + 256*(j & 3);
        x[j] = pk(ra[gi], rb[gi]);
    }
    fft_ph1(x, s[f], rev4_6(L));
    __syncthreads();
    fft_ph2(s[f], tw, L);
    __syncthreads();
    fft_ph3(s[f], tw, L, x);
    {   // store naturally-ordered results (same addresses ph3 read: no sync needed)
        int base = 4*L + (L >> 2);
        #pragma unroll
        for (int k = 0; k < 4; ++k)
            #pragma unroll
            for (int q = 0; q < 4; ++q)
                s[f][base + k + 273*q] = x[k + 4*q];
    }
    __syncthreads();                    // all 4 FFTs resident

    // transposed Hermitian unpack: keep kx = 0..512
    int ybase = 4 * rg;
    for (int e = T; e < W; e += 256) {
        int em = (N - e) & (N - 1);
        u64 va[4], vb[4];
        #pragma unroll
        for (int g = 0; g < 4; ++g) {
            float zx, zy, mxx, mxy;
            upk(s[g][P(e)],  zx, zy);
            upk(s[g][P(em)], mxx, mxy);
            va[g] = pk(0.5f*(zx + mxx), 0.5f*(zy - mxy));
            vb[g] = pk(0.5f*(zy + mxy), 0.5f*(mxx - zx));
        }
        u64* pa = g_B + ((size_t)img * WB + e) * N + ybase;
        u64* pb = pa + 512;
        *reinterpret_cast<ulonglong2*>(pa)     = make_ulonglong2(va[0], va[1]);
        *reinterpret_cast<ulonglong2*>(pa + 2) = make_ulonglong2(va[2], va[3]);
        *reinterpret_cast<ulonglong2*>(pb)     = make_ulonglong2(vb[0], vb[1]);
        *reinterpret_cast<ulonglong2*>(pb + 2) = make_ulonglong2(vb[2], vb[3]);
    }
}

// One FFT = one kept column kx. 2 columns per 128-thread block.
__global__ void __launch_bounds__(128) k_colfft(void) {
    __shared__ u64 s[2][S_SZ];
    __shared__ u64 tw[TW_SZ];
    __shared__ float m[2][N];           // shifted log-magnitudes
    __shared__ float red[8];            // 4 warps: min[0..3], max[4..7]
    int T = threadIdx.x, f = T >> 6, L = T & 63;
    #pragma unroll
    for (int j = T; j < 256; j += 128) tw[j + (j >> 4)] = g_tw[j];
    int bx  = blockIdx.x;               // img*257 + cg
    int img = bx / 257;
    int cg  = bx - img * 257;
    int kx  = 2*cg + f;                 // 0..513 (513 is padding)
    bool valid = (kx < W);
    __syncthreads();                    // tw ready

    const u64* cp = g_B + ((size_t)img * WB + kx) * N;
    // relabeled: contiguous 256B/warp loads
    u64 x[16];
    #pragma unroll
    for (int j = 0; j < 16; ++j)
        x[j] = cp[L + 64*((j >> 2) & 3) + 256*(j & 3)];
    fft_ph1(x, s[f], rev4_6(L));
    __syncthreads();
    fft_ph2(s[f], tw, L);
    __syncthreads();
    fft_ph3(s[f], tw, L, x);

    // log-magnitude straight from registers; fftshift along ky
    float mn = 3.4e38f, mx = 0.0f;
    int mbase = 4*L;
    #pragma unroll
    for (int k = 0; k < 4; ++k)
        #pragma unroll
        for (int q = 0; q < 4; ++q) {
            int cshift = (256*q + 512) & (N - 1);   // literal per q: 512,768,0,256
            float vx, vy; upk(x[k + 4*q], vx, vy);
            float mag = log1pf(sqrtf(vx*vx + vy*vy));
            m[f][mbase + k + cshift] = mag;
            mn = fminf(mn, mag); mx = fmaxf(mx, mag);
        }
    #pragma unroll
    for (int o = 16; o; o >>= 1) {
        mn = fminf(mn, __shfl_xor_sync(0xffffffffu, mn, o));
        mx = fmaxf(mx, __shfl_xor_sync(0xffffffffu, mx, o));
    }
    int wid = T >> 5;
    if ((T & 31) == 0) { red[wid] = mn; red[4 + wid] = mx; }
    __syncthreads();                    // red + m[] ready
    if (L == 0 && valid) {
        float a  = fminf(red[2*f], red[2*f + 1]);
        float c2 = fmaxf(red[4 + 2*f], red[4 + 2*f + 1]);
        int b = img / 3;
        atomicMin(&g_mn[b], __float_as_uint(a));
        atomicMax(&g_mx[b], __float_as_uint(c2));
    }

    // antialiased triangle resize along kys (ramp weights), column + mirror
    if (valid) {
        int kxs1 = (kx + 512) & (N - 1);
        int kxs2 = 512 - kx;
        float* gt1 = g_T + ((size_t)img * N + kxs1) * OUT_HW;
        float* gt2 = g_T + ((size_t)img * N + kxs2) * OUT_HW;
        for (int oy = L; oy < OUT_HW; oy += 64) {
            float sf = ((float)oy + 0.5f) * (1024.0f/224.0f) - 0.5f;
            int i0 = max(0, (int)ceilf(sf - KRAD));
            int i1 = min(N - 1, (int)floorf(sf + KRAD));
            int ip = (int)floorf(sf);
            float acc1 = 0.0f, acc2 = 0.0f, sw = 0.0f;
            float w = 1.0f - (sf - (float)i0) * KSCL;
            int i = i0;
            for (; i <= ip; ++i) {
                acc1 += w * m[f][i];
                acc2 += w * m[f][(N - i) & (N - 1)];
                sw += w; w += KSCL;
            }
            w = 1.0f - ((float)i - sf) * KSCL;
            for (; i <= i1; ++i) {
                acc1 += w * m[f][i];
                acc2 += w * m[f][(N - i) & (N - 1)];
                sw += w; w -= KSCL;
            }
            float inv = 1.0f / sw;
            gt1[oy] = acc1 * inv;
            gt2[oy] = acc2 * inv;
        }
    }
}

__global__ void __launch_bounds__(224) k_resize2(float* __restrict__ out) {
    int blk = blockIdx.x;               // img*224 + ox
    int img = blk / OUT_HW;
    int ox  = blk - img * OUT_HW;
    int oy  = threadIdx.x;
    float sf = ((float)ox + 0.5f) * (1024.0f/224.0f) - 0.5f;
    int i0 = max(0, (int)ceilf(sf - KRAD));
    int i1 = min(N - 1, (int)floorf(sf + KRAD));
    int ip = (int)floorf(sf);
    float acc = 0.0f, sw = 0.0f;
    const float* base = g_T + (size_t)img * N * OUT_HW + oy;
    float w = 1.0f - (sf - (float)i0) * KSCL;
    int i = i0;
    for (; i <= ip; ++i) { acc += w * base[(size_t)i * OUT_HW]; sw += w; w += KSCL; }
    w = 1.0f - ((float)i - sf) * KSCL;
    for (; i <= i1; ++i) { acc += w * base[(size_t)i * OUT_HW]; sw += w; w -= KSCL; }
    int b = img / 3;
    float mn = __uint_as_float(g_mn[b]);
    float mx = __uint_as_float(g_mx[b]);
    float v = (acc / sw - mn) / (mx - mn + 1e-8f);
    out[((size_t)img * OUT_HW + oy) * OUT_HW + ox] = v;
}

extern "C" void kernel_launch(void* const* d_in, const int* in_sizes, int n_in,
                              void* d_out, int out_size) {
    (void)in_sizes; (void)n_in; (void)out_size;
    const float* in = (const float*)d_in[0];
    float* out = (float*)d_out;

    k_init<<<1, 256>>>();
    k_rowfft<<<NIMG * 128, 256>>>(in);
    k_colfft<<<NIMG * 257, 128>>>();
    k_resize2<<<NIMG * OUT_HW, 224>>>(out);
}